// round 8
// baseline (speedup 1.0000x reference)
#include <cuda_runtime.h>
#include <cuda_fp16.h>
#include <cstdint>

#define N_NODES 50000
#define N_EDGES 800000
#define DIM 128
#define BCAP 64                   // bucket capacity (P(deg>64) ~ 1e-18)

// ---------------------------------------------------------------------------
// Device scratch. NOTE: g_deg relies on the zero-init of device globals at
// module load AND on aggregate_kernel resetting it to 0 after every use, so
// every execution of the launch sequence sees deg==0 (replay-safe, no prep
// zeroing pass needed).
// ---------------------------------------------------------------------------
__device__ __align__(16) __half g_H[N_NODES * DIM];   // relu(V@W^T+b), fp16
__device__ __align__(16) int g_deg[N_NODES];          // in-degree (cursor)
__device__ __align__(16) int g_bucket[N_NODES * BCAP];// src indices per dst
__device__ int g_idx32;                               // 1 if indices are int32

// ---------------------------------------------------------------------------
// dtype detect only (1 block): int64 indices < 50000 have zero high words.
// ---------------------------------------------------------------------------
__global__ void detect_kernel(const unsigned int* __restrict__ srcw) {
    __shared__ int found;
    if (threadIdx.x == 0) found = 0;
    __syncthreads();
    for (int j = threadIdx.x; j < 2048; j += blockDim.x)
        if (srcw[2 * j + 1] != 0u) found = 1;
    __syncthreads();
    if (threadIdx.x == 0) g_idx32 = found;
}

__device__ __forceinline__ int load_idx(const void* p, int e) {
    return g_idx32 ? ((const int*)p)[e] : (int)((const long long*)p)[e];
}

// ---------------------------------------------------------------------------
// Fused hist+fill: one atomic per edge, one pass over the edge list.
// ---------------------------------------------------------------------------
__global__ __launch_bounds__(256) void bucket_fill_kernel(
    const void* __restrict__ srcp, const void* __restrict__ dstp) {
    int e = blockIdx.x * blockDim.x + threadIdx.x;
    if (e >= N_EDGES) return;
    int s = load_idx(srcp, e);
    int d = load_idx(dstp, e);
    int pos = atomicAdd(&g_deg[d], 1);
    if (pos < BCAP) g_bucket[(d << 6) + pos] = s;
}

// ---------------------------------------------------------------------------
// Tensor-core GEMM + bias + ReLU (fp16 in via smem convert, fp32 acc).
// ---------------------------------------------------------------------------
#define GEMM_SMEM_BYTES (2 * 128 * 136 * 2)
#define SROW 136

__device__ __forceinline__ void ldsm_x4(uint32_t& r0, uint32_t& r1,
                                        uint32_t& r2, uint32_t& r3,
                                        uint32_t saddr) {
    asm volatile("ldmatrix.sync.aligned.m8n8.x4.shared.b16 {%0,%1,%2,%3}, [%4];"
                 : "=r"(r0), "=r"(r1), "=r"(r2), "=r"(r3) : "r"(saddr));
}

__device__ __forceinline__ void mma_f16(float* d, const uint32_t* a,
                                        const uint32_t* b) {
    asm volatile(
        "mma.sync.aligned.m16n8k16.row.col.f32.f16.f16.f32 "
        "{%0,%1,%2,%3}, {%4,%5,%6,%7}, {%8,%9}, {%0,%1,%2,%3};"
        : "+f"(d[0]), "+f"(d[1]), "+f"(d[2]), "+f"(d[3])
        : "r"(a[0]), "r"(a[1]), "r"(a[2]), "r"(a[3]), "r"(b[0]), "r"(b[1]));
}

__global__ __launch_bounds__(256, 2) void gemm_relu_tc_kernel(
    const float* __restrict__ V, const float* __restrict__ W,
    const float* __restrict__ b, __half* __restrict__ H) {
    extern __shared__ __half sh[];
    __half* Vh = sh;                  // [128][SROW]
    __half* Wh = sh + 128 * SROW;     // [128][SROW]

    const int tid  = threadIdx.x;
    const int lane = tid & 31;
    const int wid  = tid >> 5;
    const int mb   = blockIdx.x * 128;

    // ---- load + fp32->fp16 convert into smem ----
    {
        const int row  = tid >> 1;
        const int cof  = (tid & 1) * 64;
        const int node = mb + row;
        __half* vdst = Vh + row * SROW + cof;
        const float* vsrc = V + (long long)node * DIM + cof;
        #pragma unroll
        for (int i = 0; i < 16; i++) {
            float4 f = (node < N_NODES) ? *(const float4*)(vsrc + i * 4)
                                        : make_float4(0.f, 0.f, 0.f, 0.f);
            __half2 h01 = __floats2half2_rn(f.x, f.y);
            __half2 h23 = __floats2half2_rn(f.z, f.w);
            *(uint2*)(vdst + i * 4) = make_uint2(
                *reinterpret_cast<uint32_t*>(&h01),
                *reinterpret_cast<uint32_t*>(&h23));
        }
        __half* wdst = Wh + row * SROW + cof;
        const float* wsrc = W + row * DIM + cof;
        #pragma unroll
        for (int i = 0; i < 16; i++) {
            float4 f = *(const float4*)(wsrc + i * 4);
            __half2 h01 = __floats2half2_rn(f.x, f.y);
            __half2 h23 = __floats2half2_rn(f.z, f.w);
            *(uint2*)(wdst + i * 4) = make_uint2(
                *reinterpret_cast<uint32_t*>(&h01),
                *reinterpret_cast<uint32_t*>(&h23));
        }
    }
    __syncthreads();

    const int mw = (wid & 3) * 32;
    const int nw = (wid >> 2) * 64;
    const int g  = lane >> 3;

    const uint32_t vbase = (uint32_t)__cvta_generic_to_shared(Vh);
    const uint32_t wbase = (uint32_t)__cvta_generic_to_shared(Wh);

    const int a_row = mw + (lane & 7) + ((g & 1) << 3);
    const int a_col = (g >> 1) << 3;
    const int b_row = nw + (lane & 7) + ((g >> 1) << 3);
    const int b_col = (g & 1) << 3;

    float acc[2][8][4];
    #pragma unroll
    for (int mt = 0; mt < 2; mt++)
        #pragma unroll
        for (int nt = 0; nt < 8; nt++)
            #pragma unroll
            for (int r = 0; r < 4; r++) acc[mt][nt][r] = 0.f;

    #pragma unroll
    for (int ks = 0; ks < 8; ks++) {
        const int k0 = ks * 16;
        uint32_t a[2][4];
        #pragma unroll
        for (int mt = 0; mt < 2; mt++)
            ldsm_x4(a[mt][0], a[mt][1], a[mt][2], a[mt][3],
                    vbase + ((a_row + mt * 16) * SROW + k0 + a_col) * 2);
        uint32_t bf[8][2];
        #pragma unroll
        for (int np = 0; np < 4; np++) {
            uint32_t r0, r1, r2, r3;
            ldsm_x4(r0, r1, r2, r3,
                    wbase + ((b_row + np * 16) * SROW + k0 + b_col) * 2);
            bf[np * 2][0] = r0;  bf[np * 2][1] = r1;
            bf[np * 2 + 1][0] = r2;  bf[np * 2 + 1][1] = r3;
        }
        #pragma unroll
        for (int mt = 0; mt < 2; mt++)
            #pragma unroll
            for (int nt = 0; nt < 8; nt++)
                mma_f16(acc[mt][nt], a[mt], bf[nt]);
    }

    // ---- epilogue: bias + relu + fp16 store ----
    const int qr = lane >> 2;
    const int qc = (lane & 3) << 1;
    #pragma unroll
    for (int nt = 0; nt < 8; nt++) {
        const int n = nw + nt * 8 + qc;
        const float2 bb = *(const float2*)(b + n);
        #pragma unroll
        for (int mt = 0; mt < 2; mt++) {
            const int m0 = mb + mw + mt * 16 + qr;
            const float* c = acc[mt][nt];
            if (m0 < N_NODES) {
                __half2 h = __floats2half2_rn(fmaxf(c[0] + bb.x, 0.f),
                                              fmaxf(c[1] + bb.y, 0.f));
                *(__half2*)(H + m0 * DIM + n) = h;
            }
            if (m0 + 8 < N_NODES) {
                __half2 h = __floats2half2_rn(fmaxf(c[2] + bb.x, 0.f),
                                              fmaxf(c[3] + bb.y, 0.f));
                *(__half2*)(H + (m0 + 8) * DIM + n) = h;
            }
        }
    }
}

// ---------------------------------------------------------------------------
// Aggregate: one warp per dst node, half-warp per edge parity, 8-deep gather
// batching (mean degree 16 -> one batch covers a whole half-warp's edges).
// Resets g_deg[node] to 0 for the next launch/replay.
// ---------------------------------------------------------------------------
__device__ __forceinline__ unsigned hmax_u(unsigned a, unsigned b) {
    __half2 r = __hmax2(*reinterpret_cast<__half2*>(&a),
                        *reinterpret_cast<__half2*>(&b));
    return *reinterpret_cast<unsigned*>(&r);
}
__device__ __forceinline__ void vmax4(uint4& m, const uint4& h) {
    m.x = hmax_u(m.x, h.x); m.y = hmax_u(m.y, h.y);
    m.z = hmax_u(m.z, h.z); m.w = hmax_u(m.w, h.w);
}

__global__ __launch_bounds__(256) void aggregate_kernel(
    const uint4* __restrict__ H2, float* __restrict__ out) {
    const int node = blockIdx.x * 8 + (threadIdx.x >> 5);
    if (node >= N_NODES) return;
    const int lane = threadIdx.x & 31;
    const int half = lane >> 4;
    const int sub  = lane & 15;

    const int raw = g_deg[node];
    if (lane == 0) g_deg[node] = 0;       // reset for next replay
    const int deg = min(raw, BCAP);
    const int* __restrict__ bucket = g_bucket + (node << 6);

    uint4 m = make_uint4(0u, 0u, 0u, 0u);
    int j = half;
    #pragma unroll 1
    for (; j + 14 < deg; j += 16) {       // 8 edges per half-warp per iter
        int s[8];
        #pragma unroll
        for (int u = 0; u < 8; u++) s[u] = bucket[j + 2 * u];
        uint4 h[8];
        #pragma unroll
        for (int u = 0; u < 8; u++) h[u] = H2[s[u] * 16 + sub];
        #pragma unroll
        for (int u = 0; u < 8; u++) vmax4(m, h[u]);
    }
    if (j + 6 < deg) {                    // 4-deep cleanup
        int s[4];
        #pragma unroll
        for (int u = 0; u < 4; u++) s[u] = bucket[j + 2 * u];
        uint4 h[4];
        #pragma unroll
        for (int u = 0; u < 4; u++) h[u] = H2[s[u] * 16 + sub];
        #pragma unroll
        for (int u = 0; u < 4; u++) vmax4(m, h[u]);
        j += 8;
    }
    for (; j < deg; j += 2) {
        uint4 h = H2[bucket[j] * 16 + sub];
        vmax4(m, h);
    }
    m.x = hmax_u(m.x, __shfl_xor_sync(~0u, m.x, 16));
    m.y = hmax_u(m.y, __shfl_xor_sync(~0u, m.y, 16));
    m.z = hmax_u(m.z, __shfl_xor_sync(~0u, m.z, 16));
    m.w = hmax_u(m.w, __shfl_xor_sync(~0u, m.w, 16));

    if (half == 0) {
        float2 fx = __half22float2(*reinterpret_cast<__half2*>(&m.x));
        float2 fy = __half22float2(*reinterpret_cast<__half2*>(&m.y));
        float2 fz = __half22float2(*reinterpret_cast<__half2*>(&m.z));
        float2 fw = __half22float2(*reinterpret_cast<__half2*>(&m.w));
        float4* op = (float4*)(out + node * DIM + sub * 8);
        op[0] = make_float4(fx.x, fx.y, fy.x, fy.y);
        op[1] = make_float4(fz.x, fz.y, fw.x, fw.y);
    }
}

// ---------------------------------------------------------------------------
extern "C" void kernel_launch(void* const* d_in, const int* in_sizes, int n_in,
                              void* d_out, int out_size) {
    const float* V   = (const float*)d_in[0];
    const float* W   = (const float*)d_in[1];
    const float* b   = (const float*)d_in[2];
    const void*  src = d_in[3];
    const void*  dst = d_in[4];
    float* out = (float*)d_out;

    __half* H;
    cudaGetSymbolAddress((void**)&H, g_H);

    static cudaStream_t s_gemm = nullptr;
    static cudaEvent_t ev_fork = nullptr, ev_gemm = nullptr;
    if (!s_gemm) {
        cudaStreamCreateWithFlags(&s_gemm, cudaStreamNonBlocking);
        cudaEventCreateWithFlags(&ev_fork, cudaEventDisableTiming);
        cudaEventCreateWithFlags(&ev_gemm, cudaEventDisableTiming);
        cudaFuncSetAttribute(gemm_relu_tc_kernel,
                             cudaFuncAttributeMaxDynamicSharedMemorySize,
                             GEMM_SMEM_BYTES);
    }

    // Fork: GEMM (V,W,b -> H) concurrent with bucket build (src,dst).
    cudaEventRecord(ev_fork, 0);
    cudaStreamWaitEvent(s_gemm, ev_fork, 0);
    gemm_relu_tc_kernel<<<(N_NODES + 127) / 128, 256, GEMM_SMEM_BYTES, s_gemm>>>(
        V, W, b, H);
    cudaEventRecord(ev_gemm, s_gemm);

    detect_kernel<<<1, 256>>>((const unsigned int*)src);
    bucket_fill_kernel<<<(N_EDGES + 255) / 256, 256>>>(src, dst);

    // Join: aggregate needs both H and the buckets.
    cudaStreamWaitEvent(0, ev_gemm, 0);
    aggregate_kernel<<<(N_NODES + 7) / 8, 256>>>((const uint4*)H, out);
}

// round 9
// speedup vs baseline: 2.5050x; 2.5050x over previous
#include <cuda_runtime.h>
#include <cuda_fp16.h>
#include <cstdint>

#define N_NODES 50000
#define N_EDGES 800000
#define DIM 128
#define BCAP 64                   // bucket capacity (P(deg>64) ~ 1e-18)

// ---------------------------------------------------------------------------
// Device scratch
// ---------------------------------------------------------------------------
__device__ __align__(16) __half g_H[N_NODES * DIM];   // relu(V@W^T+b), fp16
__device__ __align__(16) int g_deg[N_NODES];          // in-degree (cursor)
__device__ __align__(16) int g_bucket[N_NODES * BCAP];// src indices per dst
__device__ int g_idx32;                               // 1 if indices are int32

// ---------------------------------------------------------------------------
// prep: zero degree array; block 0 detects index dtype
// (int64 indices < 50000 have all-zero high 32-bit words).
// ---------------------------------------------------------------------------
__global__ void prep_kernel(const unsigned int* __restrict__ srcw) {
    int i = blockIdx.x * blockDim.x + threadIdx.x;
    if (i < N_NODES) g_deg[i] = 0;
    if (blockIdx.x == 0) {
        __shared__ int found;
        if (threadIdx.x == 0) found = 0;
        __syncthreads();
        for (int j = threadIdx.x; j < 2048; j += blockDim.x)
            if (srcw[2 * j + 1] != 0u) found = 1;
        __syncthreads();
        if (threadIdx.x == 0) g_idx32 = found;
    }
}

__device__ __forceinline__ int load_idx(const void* p, int e) {
    return g_idx32 ? ((const int*)p)[e] : (int)((const long long*)p)[e];
}

// ---------------------------------------------------------------------------
// Fused hist+fill: one atomic per edge, one pass over the edge list.
// ---------------------------------------------------------------------------
__global__ __launch_bounds__(256) void bucket_fill_kernel(
    const void* __restrict__ srcp, const void* __restrict__ dstp) {
    int e = blockIdx.x * blockDim.x + threadIdx.x;
    if (e >= N_EDGES) return;
    int s = load_idx(srcp, e);
    int d = load_idx(dstp, e);
    int pos = atomicAdd(&g_deg[d], 1);
    if (pos < BCAP) g_bucket[(d << 6) + pos] = s;
}

// ---------------------------------------------------------------------------
// Tensor-core GEMM + bias + ReLU (fp16 in via smem convert, fp32 acc).
// ---------------------------------------------------------------------------
#define GEMM_SMEM_BYTES (2 * 128 * 136 * 2)
#define SROW 136

__device__ __forceinline__ void ldsm_x4(uint32_t& r0, uint32_t& r1,
                                        uint32_t& r2, uint32_t& r3,
                                        uint32_t saddr) {
    asm volatile("ldmatrix.sync.aligned.m8n8.x4.shared.b16 {%0,%1,%2,%3}, [%4];"
                 : "=r"(r0), "=r"(r1), "=r"(r2), "=r"(r3) : "r"(saddr));
}

__device__ __forceinline__ void mma_f16(float* d, const uint32_t* a,
                                        const uint32_t* b) {
    asm volatile(
        "mma.sync.aligned.m16n8k16.row.col.f32.f16.f16.f32 "
        "{%0,%1,%2,%3}, {%4,%5,%6,%7}, {%8,%9}, {%0,%1,%2,%3};"
        : "+f"(d[0]), "+f"(d[1]), "+f"(d[2]), "+f"(d[3])
        : "r"(a[0]), "r"(a[1]), "r"(a[2]), "r"(a[3]), "r"(b[0]), "r"(b[1]));
}

__global__ __launch_bounds__(256, 2) void gemm_relu_tc_kernel(
    const float* __restrict__ V, const float* __restrict__ W,
    const float* __restrict__ b, __half* __restrict__ H) {
    extern __shared__ __half sh[];
    __half* Vh = sh;                  // [128][SROW]
    __half* Wh = sh + 128 * SROW;     // [128][SROW]

    const int tid  = threadIdx.x;
    const int lane = tid & 31;
    const int wid  = tid >> 5;
    const int mb   = blockIdx.x * 128;

    // ---- load + fp32->fp16 convert into smem ----
    {
        const int row  = tid >> 1;
        const int cof  = (tid & 1) * 64;
        const int node = mb + row;
        __half* vdst = Vh + row * SROW + cof;
        const float* vsrc = V + (long long)node * DIM + cof;
        #pragma unroll
        for (int i = 0; i < 16; i++) {
            float4 f = (node < N_NODES) ? *(const float4*)(vsrc + i * 4)
                                        : make_float4(0.f, 0.f, 0.f, 0.f);
            __half2 h01 = __floats2half2_rn(f.x, f.y);
            __half2 h23 = __floats2half2_rn(f.z, f.w);
            *(uint2*)(vdst + i * 4) = make_uint2(
                *reinterpret_cast<uint32_t*>(&h01),
                *reinterpret_cast<uint32_t*>(&h23));
        }
        __half* wdst = Wh + row * SROW + cof;
        const float* wsrc = W + row * DIM + cof;
        #pragma unroll
        for (int i = 0; i < 16; i++) {
            float4 f = *(const float4*)(wsrc + i * 4);
            __half2 h01 = __floats2half2_rn(f.x, f.y);
            __half2 h23 = __floats2half2_rn(f.z, f.w);
            *(uint2*)(wdst + i * 4) = make_uint2(
                *reinterpret_cast<uint32_t*>(&h01),
                *reinterpret_cast<uint32_t*>(&h23));
        }
    }
    __syncthreads();

    const int mw = (wid & 3) * 32;
    const int nw = (wid >> 2) * 64;
    const int g  = lane >> 3;

    const uint32_t vbase = (uint32_t)__cvta_generic_to_shared(Vh);
    const uint32_t wbase = (uint32_t)__cvta_generic_to_shared(Wh);

    const int a_row = mw + (lane & 7) + ((g & 1) << 3);
    const int a_col = (g >> 1) << 3;
    const int b_row = nw + (lane & 7) + ((g >> 1) << 3);
    const int b_col = (g & 1) << 3;

    float acc[2][8][4];
    #pragma unroll
    for (int mt = 0; mt < 2; mt++)
        #pragma unroll
        for (int nt = 0; nt < 8; nt++)
            #pragma unroll
            for (int r = 0; r < 4; r++) acc[mt][nt][r] = 0.f;

    #pragma unroll
    for (int ks = 0; ks < 8; ks++) {
        const int k0 = ks * 16;
        uint32_t a[2][4];
        #pragma unroll
        for (int mt = 0; mt < 2; mt++)
            ldsm_x4(a[mt][0], a[mt][1], a[mt][2], a[mt][3],
                    vbase + ((a_row + mt * 16) * SROW + k0 + a_col) * 2);
        uint32_t bf[8][2];
        #pragma unroll
        for (int np = 0; np < 4; np++) {
            uint32_t r0, r1, r2, r3;
            ldsm_x4(r0, r1, r2, r3,
                    wbase + ((b_row + np * 16) * SROW + k0 + b_col) * 2);
            bf[np * 2][0] = r0;  bf[np * 2][1] = r1;
            bf[np * 2 + 1][0] = r2;  bf[np * 2 + 1][1] = r3;
        }
        #pragma unroll
        for (int mt = 0; mt < 2; mt++)
            #pragma unroll
            for (int nt = 0; nt < 8; nt++)
                mma_f16(acc[mt][nt], a[mt], bf[nt]);
    }

    // ---- epilogue: bias + relu + fp16 store ----
    const int qr = lane >> 2;
    const int qc = (lane & 3) << 1;
    #pragma unroll
    for (int nt = 0; nt < 8; nt++) {
        const int n = nw + nt * 8 + qc;
        const float2 bb = *(const float2*)(b + n);
        #pragma unroll
        for (int mt = 0; mt < 2; mt++) {
            const int m0 = mb + mw + mt * 16 + qr;
            const float* c = acc[mt][nt];
            if (m0 < N_NODES) {
                __half2 h = __floats2half2_rn(fmaxf(c[0] + bb.x, 0.f),
                                              fmaxf(c[1] + bb.y, 0.f));
                *(__half2*)(H + m0 * DIM + n) = h;
            }
            if (m0 + 8 < N_NODES) {
                __half2 h = __floats2half2_rn(fmaxf(c[2] + bb.x, 0.f),
                                              fmaxf(c[3] + bb.y, 0.f));
                *(__half2*)(H + (m0 + 8) * DIM + n) = h;
            }
        }
    }
}

// ---------------------------------------------------------------------------
// Aggregate: one warp per dst node, half-warp per edge parity.
// 8-deep gather batch held in NAMED scalars (arrays get demoted to local
// memory at this reg budget -- R8 regression). Mean degree 16 -> one batch
// covers a half-warp's whole edge share.
// ---------------------------------------------------------------------------
__device__ __forceinline__ unsigned hmax_u(unsigned a, unsigned b) {
    __half2 r = __hmax2(*reinterpret_cast<__half2*>(&a),
                        *reinterpret_cast<__half2*>(&b));
    return *reinterpret_cast<unsigned*>(&r);
}
__device__ __forceinline__ void vmax4(uint4& m, const uint4& h) {
    m.x = hmax_u(m.x, h.x); m.y = hmax_u(m.y, h.y);
    m.z = hmax_u(m.z, h.z); m.w = hmax_u(m.w, h.w);
}

__global__ __launch_bounds__(256) void aggregate_kernel(
    const uint4* __restrict__ H2, float* __restrict__ out) {
    const int node = blockIdx.x * 8 + (threadIdx.x >> 5);
    if (node >= N_NODES) return;
    const int lane = threadIdx.x & 31;
    const int half = lane >> 4;
    const int sub  = lane & 15;

    const int deg = min(g_deg[node], BCAP);
    const int* __restrict__ bucket = g_bucket + (node << 6);

    uint4 m = make_uint4(0u, 0u, 0u, 0u);
    int j = half;
    for (; j + 14 < deg; j += 16) {       // 8 edges per half-warp per iter
        const int s0 = bucket[j],      s1 = bucket[j + 2];
        const int s2 = bucket[j + 4],  s3 = bucket[j + 6];
        const int s4 = bucket[j + 8],  s5 = bucket[j + 10];
        const int s6 = bucket[j + 12], s7 = bucket[j + 14];
        const uint4 h0 = H2[s0 * 16 + sub];
        const uint4 h1 = H2[s1 * 16 + sub];
        const uint4 h2 = H2[s2 * 16 + sub];
        const uint4 h3 = H2[s3 * 16 + sub];
        const uint4 h4 = H2[s4 * 16 + sub];
        const uint4 h5 = H2[s5 * 16 + sub];
        const uint4 h6 = H2[s6 * 16 + sub];
        const uint4 h7 = H2[s7 * 16 + sub];
        vmax4(m, h0); vmax4(m, h1); vmax4(m, h2); vmax4(m, h3);
        vmax4(m, h4); vmax4(m, h5); vmax4(m, h6); vmax4(m, h7);
    }
    if (j + 6 < deg) {                    // 4-deep cleanup
        const int s0 = bucket[j],     s1 = bucket[j + 2];
        const int s2 = bucket[j + 4], s3 = bucket[j + 6];
        const uint4 h0 = H2[s0 * 16 + sub];
        const uint4 h1 = H2[s1 * 16 + sub];
        const uint4 h2 = H2[s2 * 16 + sub];
        const uint4 h3 = H2[s3 * 16 + sub];
        vmax4(m, h0); vmax4(m, h1); vmax4(m, h2); vmax4(m, h3);
        j += 8;
    }
    for (; j < deg; j += 2) {
        const uint4 h = H2[bucket[j] * 16 + sub];
        vmax4(m, h);
    }
    m.x = hmax_u(m.x, __shfl_xor_sync(~0u, m.x, 16));
    m.y = hmax_u(m.y, __shfl_xor_sync(~0u, m.y, 16));
    m.z = hmax_u(m.z, __shfl_xor_sync(~0u, m.z, 16));
    m.w = hmax_u(m.w, __shfl_xor_sync(~0u, m.w, 16));

    if (half == 0) {
        float2 fx = __half22float2(*reinterpret_cast<__half2*>(&m.x));
        float2 fy = __half22float2(*reinterpret_cast<__half2*>(&m.y));
        float2 fz = __half22float2(*reinterpret_cast<__half2*>(&m.z));
        float2 fw = __half22float2(*reinterpret_cast<__half2*>(&m.w));
        float4* op = (float4*)(out + node * DIM + sub * 8);
        op[0] = make_float4(fx.x, fx.y, fy.x, fy.y);
        op[1] = make_float4(fz.x, fz.y, fw.x, fw.y);
    }
}

// ---------------------------------------------------------------------------
extern "C" void kernel_launch(void* const* d_in, const int* in_sizes, int n_in,
                              void* d_out, int out_size) {
    const float* V   = (const float*)d_in[0];
    const float* W   = (const float*)d_in[1];
    const float* b   = (const float*)d_in[2];
    const void*  src = d_in[3];
    const void*  dst = d_in[4];
    float* out = (float*)d_out;

    __half* H;
    cudaGetSymbolAddress((void**)&H, g_H);

    static cudaStream_t s_gemm = nullptr;
    static cudaEvent_t ev_fork = nullptr, ev_gemm = nullptr;
    if (!s_gemm) {
        cudaStreamCreateWithFlags(&s_gemm, cudaStreamNonBlocking);
        cudaEventCreateWithFlags(&ev_fork, cudaEventDisableTiming);
        cudaEventCreateWithFlags(&ev_gemm, cudaEventDisableTiming);
        cudaFuncSetAttribute(gemm_relu_tc_kernel,
                             cudaFuncAttributeMaxDynamicSharedMemorySize,
                             GEMM_SMEM_BYTES);
    }

    // Fork: GEMM (V,W,b -> H) concurrent with bucket build (src,dst).
    cudaEventRecord(ev_fork, 0);
    cudaStreamWaitEvent(s_gemm, ev_fork, 0);
    gemm_relu_tc_kernel<<<(N_NODES + 127) / 128, 256, GEMM_SMEM_BYTES, s_gemm>>>(
        V, W, b, H);
    cudaEventRecord(ev_gemm, s_gemm);

    prep_kernel<<<(N_NODES + 255) / 256, 256>>>((const unsigned int*)src);
    bucket_fill_kernel<<<(N_EDGES + 255) / 256, 256>>>(src, dst);

    // Join: aggregate needs both H and the buckets.
    cudaStreamWaitEvent(0, ev_gemm, 0);
    aggregate_kernel<<<(N_NODES + 7) / 8, 256>>>((const uint4*)H, out);
}